// round 12
// baseline (speedup 1.0000x reference)
#include <cuda_runtime.h>
#include <cuda_fp16.h>
#include <math.h>
#include <stdint.h>

#define D_MODEL 1024
#define D_FF    4096
#define N_EXP   8
#define T_TOK   4096
#define XG_ROWS 9216
#define MAX_TILES 72

// ---- scratch (__device__ globals; no cudaMalloc allowed) --------------------
__device__ int   g_count[N_EXP];
__device__ int   g_off[N_EXP + 1];
__device__ int   g_rows[N_EXP * T_TOK];
__device__ float g_gate[N_EXP * T_TOK];
__device__ int   g_tileE[MAX_TILES];
__device__ int   g_tileM[MAX_TILES];
__device__ int   g_ntiles;
__device__ int   g_stok[XG_ROWS];
__device__ float g_sgate[XG_ROWS];

__device__ __half g_Xh[(size_t)T_TOK * D_MODEL];
__device__ __half g_W1h[(size_t)N_EXP * D_MODEL * D_FF];       // [E][K][N] fp16
__device__ __half g_W2h[(size_t)N_EXP * D_FF * D_MODEL];       // [E][K][N] fp16
__device__ __half g_H[(size_t)XG_ROWS * D_FF];

// ---- helpers ----------------------------------------------------------------
#define SWZ(o) ((o) ^ (((o) >> 3) & 0x70))

__device__ __forceinline__ uint32_t smem_u32(const void* p) {
    uint32_t a;
    asm("{ .reg .u64 t; cvta.to.shared.u64 t, %1; cvt.u32.u64 %0, t; }"
        : "=r"(a) : "l"(p));
    return a;
}
__device__ __forceinline__ void cp16(uint32_t dst, const void* src) {
    asm volatile("cp.async.cg.shared.global [%0], [%1], 16;"
                 :: "r"(dst), "l"(src) : "memory");
}
__device__ __forceinline__ void cp16z(uint32_t dst, const void* src, uint32_t n) {
    asm volatile("cp.async.cg.shared.global [%0], [%1], 16, %2;"
                 :: "r"(dst), "l"(src), "r"(n) : "memory");
}
__device__ __forceinline__ void ldsm4(uint32_t* r, uint32_t addr) {
    asm volatile("ldmatrix.sync.aligned.m8n8.x4.shared.b16 {%0,%1,%2,%3}, [%4];"
                 : "=r"(r[0]), "=r"(r[1]), "=r"(r[2]), "=r"(r[3]) : "r"(addr));
}
__device__ __forceinline__ void ldsm4t(uint32_t* r, uint32_t addr) {
    asm volatile("ldmatrix.sync.aligned.m8n8.x4.trans.shared.b16 {%0,%1,%2,%3}, [%4];"
                 : "=r"(r[0]), "=r"(r[1]), "=r"(r[2]), "=r"(r[3]) : "r"(addr));
}
__device__ __forceinline__ void mma_f16(float* d, const uint32_t* a, const uint32_t* b) {
    asm volatile("mma.sync.aligned.m16n8k16.row.col.f32.f16.f16.f32 "
        "{%0,%1,%2,%3}, {%4,%5,%6,%7}, {%8,%9}, {%0,%1,%2,%3};"
        : "+f"(d[0]), "+f"(d[1]), "+f"(d[2]), "+f"(d[3])
        : "r"(a[0]), "r"(a[1]), "r"(a[2]), "r"(a[3]), "r"(b[0]), "r"(b[1]));
}

// ---- streaming fp32 -> fp16, both weight tensors in one launch ---------------
__global__ void convert_weights(const float* __restrict__ W1, __half* __restrict__ d1,
                                const float* __restrict__ W2, __half* __restrict__ d2) {
    const size_t NW = (size_t)N_EXP * D_MODEL * D_FF / 8;   // per tensor, 8 elems/thr
    size_t g = (size_t)blockIdx.x * blockDim.x + threadIdx.x;
    const float* s; __half* d;
    if (g < NW) { s = W1; d = d1; }
    else        { s = W2; d = d2; g -= NW; }
    size_t i = g * 8;
    float4 a = *(const float4*)(s + i);
    float4 b = *(const float4*)(s + i + 4);
    __half2 h[4] = { __floats2half2_rn(a.x, a.y), __floats2half2_rn(a.z, a.w),
                     __floats2half2_rn(b.x, b.y), __floats2half2_rn(b.z, b.w) };
    *(uint4*)(d + i) = *(uint4*)h;
}

// ---- router (fused x -> fp16 convert) ----------------------------------------
__global__ void router_kernel(const float* __restrict__ x,
                              const float* __restrict__ Wr) {
    int tok  = (blockIdx.x * blockDim.x + threadIdx.x) >> 5;
    int lane = threadIdx.x & 31;
    if (tok >= T_TOK) return;
    const float* xr = x + (size_t)tok * D_MODEL;
    __half* xh = g_Xh + (size_t)tok * D_MODEL;
    float acc[N_EXP];
#pragma unroll
    for (int e = 0; e < N_EXP; e++) acc[e] = 0.f;
    for (int d = lane; d < D_MODEL; d += 32) {
        float xv = xr[d];
        xh[d] = __float2half_rn(xv);
        float4 w0 = *(const float4*)(Wr + (size_t)d * N_EXP);
        float4 w1 = *(const float4*)(Wr + (size_t)d * N_EXP + 4);
        acc[0] += xv * w0.x; acc[1] += xv * w0.y;
        acc[2] += xv * w0.z; acc[3] += xv * w0.w;
        acc[4] += xv * w1.x; acc[5] += xv * w1.y;
        acc[6] += xv * w1.z; acc[7] += xv * w1.w;
    }
#pragma unroll
    for (int e = 0; e < N_EXP; e++)
#pragma unroll
        for (int o = 16; o > 0; o >>= 1)
            acc[e] += __shfl_xor_sync(0xffffffffu, acc[e], o);
    if (lane == 0) {
        int e1 = 0; float l1 = acc[0];
#pragma unroll
        for (int e = 1; e < N_EXP; e++)
            if (acc[e] > l1) { l1 = acc[e]; e1 = e; }
        int e2 = (e1 == 0) ? 1 : 0; float l2 = acc[e2];
#pragma unroll
        for (int e = 0; e < N_EXP; e++)
            if (e != e1 && acc[e] > l2) { l2 = acc[e]; e2 = e; }
        float g1 = 1.f / (1.f + expf(l2 - l1));
        float g2 = 1.f - g1;
        int p1 = atomicAdd(&g_count[e1], 1);
        g_rows[e1 * T_TOK + p1] = tok; g_gate[e1 * T_TOK + p1] = g1;
        int p2 = atomicAdd(&g_count[e2], 1);
        g_rows[e2 * T_TOK + p2] = tok; g_gate[e2 * T_TOK + p2] = g2;
    }
}

// offsets (recomputed per block) + slot metadata, one kernel
__global__ void offsets_slots() {
    __shared__ int soff[N_EXP + 1];
    if (threadIdx.x == 0) {
        int s = 0, t = 0;
        for (int e = 0; e < N_EXP; e++) {
            soff[e] = s;
            int ct = (g_count[e] + 127) >> 7;
            if (blockIdx.x == 0)
                for (int m = 0; m < ct; m++) { g_tileE[t] = e; g_tileM[t] = m << 7; t++; }
            s += ct << 7;
        }
        soff[N_EXP] = s;
        if (blockIdx.x == 0) {
            g_ntiles = t;
            for (int e = 0; e <= N_EXP; e++) g_off[e] = soff[e];
        }
    }
    __syncthreads();
    int r = blockIdx.x * 256 + threadIdx.x;
    if (r >= XG_ROWS) return;
    int e = 0;
#pragma unroll
    for (int k = 1; k < N_EXP; k++) if (r >= soff[k]) e = k;
    int i = r - soff[e];
    int tok = (r < soff[N_EXP] && i < g_count[e]) ? g_rows[e * T_TOK + i] : -1;
    g_stok[r]  = tok;
    g_sgate[r] = (tok >= 0) ? g_gate[e * T_TOK + i] : 0.f;
}

// ---------------------------------------------------------------------------
// Persistent fp16 mma.sync GEMM: 128x128 tile, 256 threads, BK=64, 3-stage,
// 2 CTAs/SM, grid-stride tile loop (no wave quantization).
// Stage (32 KB): A 16K | B 16K
static constexpr int STG_BYTES = 32768;
static constexpr int SMEM_GEMM = 3 * STG_BYTES;

#define LOAD_STAGE(s, ktile) do {                                              \
    uint32_t st_ = sb + (uint32_t)(s) * STG_BYTES;                             \
    size_t koffA_ = (size_t)(ktile) * 128;                                     \
    size_t koffB_ = (size_t)(ktile) * 64 * NTOT * 2;                           \
    _Pragma("unroll")                                                          \
    for (int j_ = 0; j_ < 4; j_++)                                             \
        cp16z(st_ + aphys[j_], asrc[j_] + koffA_, asz[j_]);                    \
    _Pragma("unroll")                                                          \
    for (int j_ = 0; j_ < 4; j_++)                                             \
        cp16(st_ + 16384 + bphys + (uint32_t)j_ * (16 * 256),                  \
             bsrc + koffB_ + (size_t)j_ * 16 * NTOT * 2);                      \
    asm volatile("cp.async.commit_group;" ::: "memory");                       \
} while (0)

template<int PASS>
__global__ void __launch_bounds__(256, 2)
gemm_mma(const __half* __restrict__ Ax, const __half* __restrict__ Bx,
         const float* __restrict__ bias, float* __restrict__ out)
{
    constexpr int KTOT = (PASS == 0) ? D_MODEL : D_FF;
    constexpr int NTOT = (PASS == 0) ? D_FF : D_MODEL;
    constexpr int KIT  = KTOT / 64;
    constexpr int NT   = NTOT / 128;

    extern __shared__ char smem[];
    uint32_t sb = smem_u32(smem);

    int tid = threadIdx.x;
    int wid = tid >> 5, lane = tid & 31;
    int wm = wid >> 2, wn = wid & 3;       // warps 2x4; warp tile 64x32

    // lane constants
    uint32_t acb = (tid & 7) << 4;
    int arb = tid >> 3;
    uint32_t aphys[4];
#pragma unroll
    for (int j = 0; j < 4; j++) aphys[j] = SWZ((arb + 32 * j) * 128 + acb);
    int br = tid >> 4, bc = tid & 15;
    uint32_t bphys = (uint32_t)br * 256 + (uint32_t)((bc ^ (br & 7)) << 4);

    int krb = (lane & 7) + ((lane >> 4) << 3);
    int nc  = (lane >> 3) & 1;
    uint32_t bck[2];
    bck[0] = (uint32_t)(((wn * 4 + 0 + nc) ^ (lane & 7)) << 4);
    bck[1] = (uint32_t)(((wn * 4 + 2 + nc) ^ (lane & 7)) << 4);

    int totalTiles = g_ntiles * NT;

    for (int tau = blockIdx.x; tau < totalTiles; tau += gridDim.x) {
        int tt = tau / NT, nx = tau - tt * NT;
        int e     = g_tileE[tt];
        int rowA0 = g_off[e] + g_tileM[tt];
        int n0    = nx * 128;

        const char* asrc[4];
        uint32_t asz[4];
#pragma unroll
        for (int j = 0; j < 4; j++) {
            int r = arb + 32 * j;
            if (PASS == 0) {
                int tk = g_stok[rowA0 + r];
                asz[j]  = (tk >= 0) ? 16u : 0u;
                asrc[j] = (const char*)Ax + ((size_t)max(tk, 0) * KTOT) * 2 + acb;
            } else {
                asz[j]  = 16u;
                asrc[j] = (const char*)Ax + ((size_t)(rowA0 + r) * KTOT) * 2 + acb;
            }
        }
        const char* bsrc = (const char*)Bx
            + ((size_t)(e * KTOT + br) * NTOT + n0) * 2 + (size_t)bc * 16;

        float acc[4][4][4];
#pragma unroll
        for (int a = 0; a < 4; a++)
#pragma unroll
            for (int b = 0; b < 4; b++)
#pragma unroll
                for (int c = 0; c < 4; c++) acc[a][b][c] = 0.f;

        LOAD_STAGE(0, 0);
        LOAD_STAGE(1, 1);

#pragma unroll 1
        for (int kt = 0; kt < KIT; kt++) {
            if (kt + 1 < KIT) asm volatile("cp.async.wait_group 1;" ::: "memory");
            else              asm volatile("cp.async.wait_group 0;" ::: "memory");
            __syncthreads();
            int s = kt % 3;
            if (kt + 2 < KIT) { int s2 = (kt + 2) % 3; LOAD_STAGE(s2, kt + 2); }
            uint32_t sA = sb + (uint32_t)s * STG_BYTES;
            uint32_t sB = sA + 16384;
#pragma unroll
            for (int k16 = 0; k16 < 4; k16++) {
                uint32_t b_f[2][4];
                uint32_t krow = (uint32_t)(k16 * 16 + krb) * 256;
#pragma unroll
                for (int nt = 0; nt < 2; nt++)
                    ldsm4t(b_f[nt], sB + krow + bck[nt]);
#pragma unroll
                for (int mt = 0; mt < 4; mt++) {
                    uint32_t a_f[4];
                    uint32_t ad = sA + SWZ((wm * 64 + mt * 16 + (lane & 15)) * 128
                                           + k16 * 32 + (lane >> 4) * 16);
                    ldsm4(a_f, ad);
#pragma unroll
                    for (int n8 = 0; n8 < 4; n8++) {
                        int nt = n8 >> 1, hf = n8 & 1;
                        uint32_t bb[2] = { b_f[nt][hf], b_f[nt][2 + hf] };
                        mma_f16(acc[mt][n8], a_f, bb);
                    }
                }
            }
        }

        // ---- epilogue ----
        const float* bp = bias + (size_t)e * NTOT;
#pragma unroll
        for (int mt = 0; mt < 4; mt++) {
            int r0 = wm * 64 + mt * 16 + (lane >> 2);
#pragma unroll
            for (int n8 = 0; n8 < 4; n8++) {
                int cg = n0 + wn * 32 + n8 * 8 + (lane & 3) * 2;
                float* a = acc[mt][n8];
                float bb0 = bp[cg], bb1 = bp[cg + 1];
                int row = rowA0 + r0;
                if (PASS == 0) {
                    float v0 = fmaxf(a[0] + bb0, 0.f), v1 = fmaxf(a[1] + bb1, 0.f);
                    float v2 = fmaxf(a[2] + bb0, 0.f), v3 = fmaxf(a[3] + bb1, 0.f);
                    *(__half2*)(g_H + (size_t)row * D_FF + cg)       = __floats2half2_rn(v0, v1);
                    *(__half2*)(g_H + (size_t)(row + 8) * D_FF + cg) = __floats2half2_rn(v2, v3);
                } else {
                    int tok0 = g_stok[row], tok1 = g_stok[row + 8];
                    if (tok0 >= 0) {
                        float g = g_sgate[row];
                        atomicAdd(out + (size_t)tok0 * D_MODEL + cg,     g * (a[0] + bb0));
                        atomicAdd(out + (size_t)tok0 * D_MODEL + cg + 1, g * (a[1] + bb1));
                    }
                    if (tok1 >= 0) {
                        float g = g_sgate[row + 8];
                        atomicAdd(out + (size_t)tok1 * D_MODEL + cg,     g * (a[2] + bb0));
                        atomicAdd(out + (size_t)tok1 * D_MODEL + cg + 1, g * (a[3] + bb1));
                    }
                }
            }
        }
        __syncthreads();   // stage buffers reused by next tile's prime
    }
}

// ---------------------------------------------------------------------------
extern "C" void kernel_launch(void* const* d_in, const int* in_sizes, int n_in,
                              void* d_out, int out_size) {
    const float* x  = (const float*)d_in[0];
    const float* Wr = (const float*)d_in[1];
    const float* W1 = (const float*)d_in[2];
    const float* b1 = (const float*)d_in[3];
    const float* W2 = (const float*)d_in[4];
    const float* b2 = (const float*)d_in[5];
    float* out = (float*)d_out;

    void *pW1, *pW2, *pXh, *pH, *pCnt;
    cudaGetSymbolAddress(&pW1, g_W1h);
    cudaGetSymbolAddress(&pW2, g_W2h);
    cudaGetSymbolAddress(&pXh, g_Xh);
    cudaGetSymbolAddress(&pH,  g_H);
    cudaGetSymbolAddress(&pCnt, g_count);

    int nsm = 148;
    cudaDeviceGetAttribute(&nsm, cudaDevAttrMultiProcessorCount, 0);

    cudaFuncSetAttribute(gemm_mma<0>, cudaFuncAttributeMaxDynamicSharedMemorySize, SMEM_GEMM);
    cudaFuncSetAttribute(gemm_mma<1>, cudaFuncAttributeMaxDynamicSharedMemorySize, SMEM_GEMM);

    cudaMemsetAsync(out, 0, (size_t)out_size * sizeof(float));
    cudaMemsetAsync(pCnt, 0, N_EXP * sizeof(int));

    // one launch for both weight converts
    convert_weights<<<(int)(2 * ((size_t)N_EXP * D_MODEL * D_FF / 8) / 256), 256>>>(
        W1, (__half*)pW1, W2, (__half*)pW2);

    router_kernel<<<T_TOK / 8, 256>>>(x, Wr);
    offsets_slots<<<XG_ROWS / 256, 256>>>();

    gemm_mma<0><<<2 * nsm, 256, SMEM_GEMM>>>((const __half*)pXh, (const __half*)pW1, b1, out);
    gemm_mma<1><<<2 * nsm, 256, SMEM_GEMM>>>((const __half*)pH,  (const __half*)pW2, b2, out);
}

// round 13
// speedup vs baseline: 1.0074x; 1.0074x over previous
#include <cuda_runtime.h>
#include <cuda_fp16.h>
#include <math.h>
#include <stdint.h>

#define D_MODEL 1024
#define D_FF    4096
#define N_EXP   8
#define T_TOK   4096
#define XG_ROWS 9216
#define MAX_TILES 72
#define KCH     1024          // split-K chunk (pass 1): 4 chunks of 1024

// ---- scratch (__device__ globals; no cudaMalloc allowed) --------------------
__device__ int   g_count[N_EXP];
__device__ int   g_off[N_EXP + 1];
__device__ int   g_rows[N_EXP * T_TOK];
__device__ float g_gate[N_EXP * T_TOK];
__device__ int   g_tileE[MAX_TILES];
__device__ int   g_tileM[MAX_TILES];
__device__ int   g_ntiles;
__device__ int   g_stok[XG_ROWS];
__device__ float g_sgate[XG_ROWS];

__device__ __half g_Xh[(size_t)T_TOK * D_MODEL];
__device__ __half g_W1h[(size_t)N_EXP * D_MODEL * D_FF];       // [E][K][N] fp16
__device__ __half g_W2h[(size_t)N_EXP * D_FF * D_MODEL];       // [E][K][N] fp16
__device__ __half g_H[(size_t)XG_ROWS * D_FF];

// ---- helpers ----------------------------------------------------------------
#define SWZ(o) ((o) ^ (((o) >> 3) & 0x70))

__device__ __forceinline__ uint32_t smem_u32(const void* p) {
    uint32_t a;
    asm("{ .reg .u64 t; cvta.to.shared.u64 t, %1; cvt.u32.u64 %0, t; }"
        : "=r"(a) : "l"(p));
    return a;
}
__device__ __forceinline__ void cp16(uint32_t dst, const void* src) {
    asm volatile("cp.async.cg.shared.global [%0], [%1], 16;"
                 :: "r"(dst), "l"(src) : "memory");
}
__device__ __forceinline__ void cp16z(uint32_t dst, const void* src, uint32_t n) {
    asm volatile("cp.async.cg.shared.global [%0], [%1], 16, %2;"
                 :: "r"(dst), "l"(src), "r"(n) : "memory");
}
__device__ __forceinline__ void ldsm4(uint32_t* r, uint32_t addr) {
    asm volatile("ldmatrix.sync.aligned.m8n8.x4.shared.b16 {%0,%1,%2,%3}, [%4];"
                 : "=r"(r[0]), "=r"(r[1]), "=r"(r[2]), "=r"(r[3]) : "r"(addr));
}
__device__ __forceinline__ void ldsm4t(uint32_t* r, uint32_t addr) {
    asm volatile("ldmatrix.sync.aligned.m8n8.x4.trans.shared.b16 {%0,%1,%2,%3}, [%4];"
                 : "=r"(r[0]), "=r"(r[1]), "=r"(r[2]), "=r"(r[3]) : "r"(addr));
}
__device__ __forceinline__ void mma_f16(float* d, const uint32_t* a, const uint32_t* b) {
    asm volatile("mma.sync.aligned.m16n8k16.row.col.f32.f16.f16.f32 "
        "{%0,%1,%2,%3}, {%4,%5,%6,%7}, {%8,%9}, {%0,%1,%2,%3};"
        : "+f"(d[0]), "+f"(d[1]), "+f"(d[2]), "+f"(d[3])
        : "r"(a[0]), "r"(a[1]), "r"(a[2]), "r"(a[3]), "r"(b[0]), "r"(b[1]));
}

// ---- streaming fp32 -> fp16, both weight tensors in one launch ---------------
__global__ void convert_weights(const float* __restrict__ W1, __half* __restrict__ d1,
                                const float* __restrict__ W2, __half* __restrict__ d2) {
    const size_t NW = (size_t)N_EXP * D_MODEL * D_FF / 8;
    size_t g = (size_t)blockIdx.x * blockDim.x + threadIdx.x;
    const float* s; __half* d;
    if (g < NW) { s = W1; d = d1; }
    else        { s = W2; d = d2; g -= NW; }
    size_t i = g * 8;
    float4 a = *(const float4*)(s + i);
    float4 b = *(const float4*)(s + i + 4);
    __half2 h[4] = { __floats2half2_rn(a.x, a.y), __floats2half2_rn(a.z, a.w),
                     __floats2half2_rn(b.x, b.y), __floats2half2_rn(b.z, b.w) };
    *(uint4*)(d + i) = *(uint4*)h;
}

// ---- router (fused x -> fp16 convert) ----------------------------------------
__global__ void router_kernel(const float* __restrict__ x,
                              const float* __restrict__ Wr) {
    int tok  = (blockIdx.x * blockDim.x + threadIdx.x) >> 5;
    int lane = threadIdx.x & 31;
    if (tok >= T_TOK) return;
    const float* xr = x + (size_t)tok * D_MODEL;
    __half* xh = g_Xh + (size_t)tok * D_MODEL;
    float acc[N_EXP];
#pragma unroll
    for (int e = 0; e < N_EXP; e++) acc[e] = 0.f;
    for (int d = lane; d < D_MODEL; d += 32) {
        float xv = xr[d];
        xh[d] = __float2half_rn(xv);
        float4 w0 = *(const float4*)(Wr + (size_t)d * N_EXP);
        float4 w1 = *(const float4*)(Wr + (size_t)d * N_EXP + 4);
        acc[0] += xv * w0.x; acc[1] += xv * w0.y;
        acc[2] += xv * w0.z; acc[3] += xv * w0.w;
        acc[4] += xv * w1.x; acc[5] += xv * w1.y;
        acc[6] += xv * w1.z; acc[7] += xv * w1.w;
    }
#pragma unroll
    for (int e = 0; e < N_EXP; e++)
#pragma unroll
        for (int o = 16; o > 0; o >>= 1)
            acc[e] += __shfl_xor_sync(0xffffffffu, acc[e], o);
    if (lane == 0) {
        int e1 = 0; float l1 = acc[0];
#pragma unroll
        for (int e = 1; e < N_EXP; e++)
            if (acc[e] > l1) { l1 = acc[e]; e1 = e; }
        int e2 = (e1 == 0) ? 1 : 0; float l2 = acc[e2];
#pragma unroll
        for (int e = 0; e < N_EXP; e++)
            if (e != e1 && acc[e] > l2) { l2 = acc[e]; e2 = e; }
        float g1 = 1.f / (1.f + expf(l2 - l1));
        float g2 = 1.f - g1;
        int p1 = atomicAdd(&g_count[e1], 1);
        g_rows[e1 * T_TOK + p1] = tok; g_gate[e1 * T_TOK + p1] = g1;
        int p2 = atomicAdd(&g_count[e2], 1);
        g_rows[e2 * T_TOK + p2] = tok; g_gate[e2 * T_TOK + p2] = g2;
    }
}

// offsets (recomputed per block) + slot metadata, one kernel
__global__ void offsets_slots() {
    __shared__ int soff[N_EXP + 1];
    if (threadIdx.x == 0) {
        int s = 0, t = 0;
        for (int e = 0; e < N_EXP; e++) {
            soff[e] = s;
            int ct = (g_count[e] + 127) >> 7;
            if (blockIdx.x == 0)
                for (int m = 0; m < ct; m++) { g_tileE[t] = e; g_tileM[t] = m << 7; t++; }
            s += ct << 7;
        }
        soff[N_EXP] = s;
        if (blockIdx.x == 0) {
            g_ntiles = t;
            for (int e = 0; e <= N_EXP; e++) g_off[e] = soff[e];
        }
    }
    __syncthreads();
    int r = blockIdx.x * 256 + threadIdx.x;
    if (r >= XG_ROWS) return;
    int e = 0;
#pragma unroll
    for (int k = 1; k < N_EXP; k++) if (r >= soff[k]) e = k;
    int i = r - soff[e];
    int tok = (r < soff[N_EXP] && i < g_count[e]) ? g_rows[e * T_TOK + i] : -1;
    g_stok[r]  = tok;
    g_sgate[r] = (tok >= 0) ? g_gate[e * T_TOK + i] : 0.f;
}

// ---------------------------------------------------------------------------
// fp16 mma.sync GEMM: 128x128 tile, 256 threads, BK=64, 3-stage, 2 CTAs/SM.
// PASS 0: full K=1024.  PASS 1: split-K, chunk = blockIdx.z * KCH, 4 chunks;
// each chunk atomically adds gate*(partial [+ bias on chunk 0]) into out.
// Stage (32 KB): A 16K | B 16K
static constexpr int STG_BYTES = 32768;
static constexpr int SMEM_GEMM = 3 * STG_BYTES;

#define LOAD_STAGE(s, ktile) do {                                              \
    uint32_t st_ = sb + (uint32_t)(s) * STG_BYTES;                             \
    size_t koffA_ = (size_t)(ktile) * 128;                                     \
    size_t koffB_ = (size_t)(ktile) * 64 * NTOT * 2;                           \
    _Pragma("unroll")                                                          \
    for (int j_ = 0; j_ < 4; j_++)                                             \
        cp16z(st_ + aphys[j_], asrc[j_] + koffA_, asz[j_]);                    \
    _Pragma("unroll")                                                          \
    for (int j_ = 0; j_ < 4; j_++)                                             \
        cp16(st_ + 16384 + bphys + (uint32_t)j_ * (16 * 256),                  \
             bsrc + koffB_ + (size_t)j_ * 16 * NTOT * 2);                      \
    asm volatile("cp.async.commit_group;" ::: "memory");                       \
} while (0)

template<int PASS>
__global__ void __launch_bounds__(256, 2)
gemm_mma(const __half* __restrict__ Ax, const __half* __restrict__ Bx,
         const float* __restrict__ bias, float* __restrict__ out)
{
    constexpr int KTOT = (PASS == 0) ? D_MODEL : D_FF;
    constexpr int NTOT = (PASS == 0) ? D_FF : D_MODEL;
    constexpr int KIT  = 16;                       // 16 x 64 = 1024 per chunk

    int t = blockIdx.y;
    if (t >= g_ntiles) return;
    int e     = g_tileE[t];
    int rowA0 = g_off[e] + g_tileM[t];
    int n0    = blockIdx.x * 128;
    int kbase = (PASS == 1) ? (int)blockIdx.z * KCH : 0;

    extern __shared__ char smem[];
    uint32_t sb = smem_u32(smem);

    int tid = threadIdx.x;
    int wid = tid >> 5, lane = tid & 31;
    int wm = wid >> 2, wn = wid & 3;       // warps 2x4; warp tile 64x32

    // ---- producer constants ----
    uint32_t acb = (tid & 7) << 4;
    int arb = tid >> 3;
    uint32_t aphys[4];
    const char* asrc[4];
    uint32_t asz[4];
#pragma unroll
    for (int j = 0; j < 4; j++) {
        int r = arb + 32 * j;
        aphys[j] = SWZ(r * 128 + acb);
        if (PASS == 0) {
            int tk = g_stok[rowA0 + r];
            asz[j]  = (tk >= 0) ? 16u : 0u;
            asrc[j] = (const char*)Ax + ((size_t)max(tk, 0) * KTOT + kbase) * 2 + acb;
        } else {
            asz[j]  = 16u;
            asrc[j] = (const char*)Ax + ((size_t)(rowA0 + r) * KTOT + kbase) * 2 + acb;
        }
    }
    int br = tid >> 4, bc = tid & 15;
    uint32_t bphys = (uint32_t)br * 256 + (uint32_t)((bc ^ (br & 7)) << 4);
    const char* bsrc = (const char*)Bx
        + ((size_t)(e * KTOT + kbase + br) * NTOT + n0) * 2 + (size_t)bc * 16;

    // ---- consumer fragment constants (B trans) ----
    int krb = (lane & 7) + ((lane >> 4) << 3);
    int nc  = (lane >> 3) & 1;
    uint32_t bck[2];
    bck[0] = (uint32_t)(((wn * 4 + 0 + nc) ^ (lane & 7)) << 4);
    bck[1] = (uint32_t)(((wn * 4 + 2 + nc) ^ (lane & 7)) << 4);

    float acc[4][4][4];
#pragma unroll
    for (int a = 0; a < 4; a++)
#pragma unroll
        for (int b = 0; b < 4; b++)
#pragma unroll
            for (int c = 0; c < 4; c++) acc[a][b][c] = 0.f;

    LOAD_STAGE(0, 0);
    LOAD_STAGE(1, 1);

#pragma unroll 1
    for (int kt = 0; kt < KIT; kt++) {
        if (kt + 1 < KIT) asm volatile("cp.async.wait_group 1;" ::: "memory");
        else              asm volatile("cp.async.wait_group 0;" ::: "memory");
        __syncthreads();
        int s = kt % 3;
        if (kt + 2 < KIT) { int s2 = (kt + 2) % 3; LOAD_STAGE(s2, kt + 2); }
        uint32_t sA = sb + (uint32_t)s * STG_BYTES;
        uint32_t sB = sA + 16384;
#pragma unroll
        for (int k16 = 0; k16 < 4; k16++) {
            uint32_t b_f[2][4];
            uint32_t krow = (uint32_t)(k16 * 16 + krb) * 256;
#pragma unroll
            for (int nt = 0; nt < 2; nt++)
                ldsm4t(b_f[nt], sB + krow + bck[nt]);
#pragma unroll
            for (int mt = 0; mt < 4; mt++) {
                uint32_t a_f[4];
                uint32_t ad = sA + SWZ((wm * 64 + mt * 16 + (lane & 15)) * 128
                                       + k16 * 32 + (lane >> 4) * 16);
                ldsm4(a_f, ad);
#pragma unroll
                for (int n8 = 0; n8 < 4; n8++) {
                    int nt = n8 >> 1, hf = n8 & 1;
                    uint32_t bb[2] = { b_f[nt][hf], b_f[nt][2 + hf] };
                    mma_f16(acc[mt][n8], a_f, bb);
                }
            }
        }
    }

    // ---- epilogue ----
    const float* bp = bias + (size_t)e * NTOT;
    float bscale = (PASS == 1 && kbase != 0) ? 0.f : 1.f;   // bias once per output
#pragma unroll
    for (int mt = 0; mt < 4; mt++) {
        int r0 = wm * 64 + mt * 16 + (lane >> 2);
#pragma unroll
        for (int n8 = 0; n8 < 4; n8++) {
            int cg = n0 + wn * 32 + n8 * 8 + (lane & 3) * 2;
            float* a = acc[mt][n8];
            float bb0 = bp[cg] * bscale, bb1 = bp[cg + 1] * bscale;
            int row = rowA0 + r0;
            if (PASS == 0) {
                float v0 = fmaxf(a[0] + bb0, 0.f), v1 = fmaxf(a[1] + bb1, 0.f);
                float v2 = fmaxf(a[2] + bb0, 0.f), v3 = fmaxf(a[3] + bb1, 0.f);
                *(__half2*)(g_H + (size_t)row * D_FF + cg)       = __floats2half2_rn(v0, v1);
                *(__half2*)(g_H + (size_t)(row + 8) * D_FF + cg) = __floats2half2_rn(v2, v3);
            } else {
                int tok0 = g_stok[row], tok1 = g_stok[row + 8];
                if (tok0 >= 0) {
                    float g = g_sgate[row];
                    atomicAdd(out + (size_t)tok0 * D_MODEL + cg,     g * (a[0] + bb0));
                    atomicAdd(out + (size_t)tok0 * D_MODEL + cg + 1, g * (a[1] + bb1));
                }
                if (tok1 >= 0) {
                    float g = g_sgate[row + 8];
                    atomicAdd(out + (size_t)tok1 * D_MODEL + cg,     g * (a[2] + bb0));
                    atomicAdd(out + (size_t)tok1 * D_MODEL + cg + 1, g * (a[3] + bb1));
                }
            }
        }
    }
}

// ---------------------------------------------------------------------------
extern "C" void kernel_launch(void* const* d_in, const int* in_sizes, int n_in,
                              void* d_out, int out_size) {
    const float* x  = (const float*)d_in[0];
    const float* Wr = (const float*)d_in[1];
    const float* W1 = (const float*)d_in[2];
    const float* b1 = (const float*)d_in[3];
    const float* W2 = (const float*)d_in[4];
    const float* b2 = (const float*)d_in[5];
    float* out = (float*)d_out;

    void *pW1, *pW2, *pXh, *pH, *pCnt;
    cudaGetSymbolAddress(&pW1, g_W1h);
    cudaGetSymbolAddress(&pW2, g_W2h);
    cudaGetSymbolAddress(&pXh, g_Xh);
    cudaGetSymbolAddress(&pH,  g_H);
    cudaGetSymbolAddress(&pCnt, g_count);

    cudaFuncSetAttribute(gemm_mma<0>, cudaFuncAttributeMaxDynamicSharedMemorySize, SMEM_GEMM);
    cudaFuncSetAttribute(gemm_mma<1>, cudaFuncAttributeMaxDynamicSharedMemorySize, SMEM_GEMM);

    cudaMemsetAsync(out, 0, (size_t)out_size * sizeof(float));
    cudaMemsetAsync(pCnt, 0, N_EXP * sizeof(int));

    convert_weights<<<(int)(2 * ((size_t)N_EXP * D_MODEL * D_FF / 8) / 256), 256>>>(
        W1, (__half*)pW1, W2, (__half*)pW2);

    router_kernel<<<T_TOK / 8, 256>>>(x, Wr);
    offsets_slots<<<XG_ROWS / 256, 256>>>();

    gemm_mma<0><<<dim3(D_FF / 128, MAX_TILES), 256, SMEM_GEMM>>>(
        (const __half*)pXh, (const __half*)pW1, b1, out);
    gemm_mma<1><<<dim3(D_MODEL / 128, MAX_TILES, D_FF / KCH), 256, SMEM_GEMM>>>(
        (const __half*)pH, (const __half*)pW2, b2, out);
}

// round 14
// speedup vs baseline: 1.0479x; 1.0403x over previous
#include <cuda_runtime.h>
#include <cuda_fp16.h>
#include <math.h>
#include <stdint.h>

#define D_MODEL 1024
#define D_FF    4096
#define N_EXP   8
#define T_TOK   4096
#define XG_ROWS 9216
#define MAX_TILES 72
#define KCH1    2048          // pass-1 split-K chunk (2 chunks)

// ---- scratch (__device__ globals; no cudaMalloc allowed) --------------------
__device__ int   g_count[N_EXP];
__device__ int   g_off[N_EXP + 1];
__device__ int   g_rows[N_EXP * T_TOK];
__device__ float g_gate[N_EXP * T_TOK];
__device__ int   g_tileE[MAX_TILES];
__device__ int   g_tileM[MAX_TILES];
__device__ int   g_ntiles;
__device__ int   g_stok[XG_ROWS];
__device__ float g_sgate[XG_ROWS];
__device__ int   g_tokn[T_TOK];
__device__ int   g_tokslot[T_TOK * 2];

__device__ __half g_Xh[(size_t)T_TOK * D_MODEL];
__device__ __half g_W1h[(size_t)N_EXP * D_MODEL * D_FF];       // [E][K][N] fp16
__device__ __half g_W2h[(size_t)N_EXP * D_FF * D_MODEL];       // [E][K][N] fp16
__device__ __half g_H[(size_t)XG_ROWS * D_FF];
__device__ float  g_Y[(size_t)2 * XG_ROWS * D_MODEL];          // pass-1 partials

// ---- helpers ----------------------------------------------------------------
#define SWZ(o) ((o) ^ (((o) >> 3) & 0x70))

__device__ __forceinline__ uint32_t smem_u32(const void* p) {
    uint32_t a;
    asm("{ .reg .u64 t; cvta.to.shared.u64 t, %1; cvt.u32.u64 %0, t; }"
        : "=r"(a) : "l"(p));
    return a;
}
__device__ __forceinline__ void cp16(uint32_t dst, const void* src) {
    asm volatile("cp.async.cg.shared.global [%0], [%1], 16;"
                 :: "r"(dst), "l"(src) : "memory");
}
__device__ __forceinline__ void cp16z(uint32_t dst, const void* src, uint32_t n) {
    asm volatile("cp.async.cg.shared.global [%0], [%1], 16, %2;"
                 :: "r"(dst), "l"(src), "r"(n) : "memory");
}
__device__ __forceinline__ void ldsm4(uint32_t* r, uint32_t addr) {
    asm volatile("ldmatrix.sync.aligned.m8n8.x4.shared.b16 {%0,%1,%2,%3}, [%4];"
                 : "=r"(r[0]), "=r"(r[1]), "=r"(r[2]), "=r"(r[3]) : "r"(addr));
}
__device__ __forceinline__ void ldsm4t(uint32_t* r, uint32_t addr) {
    asm volatile("ldmatrix.sync.aligned.m8n8.x4.trans.shared.b16 {%0,%1,%2,%3}, [%4];"
                 : "=r"(r[0]), "=r"(r[1]), "=r"(r[2]), "=r"(r[3]) : "r"(addr));
}
__device__ __forceinline__ void mma_f16(float* d, const uint32_t* a, const uint32_t* b) {
    asm volatile("mma.sync.aligned.m16n8k16.row.col.f32.f16.f16.f32 "
        "{%0,%1,%2,%3}, {%4,%5,%6,%7}, {%8,%9}, {%0,%1,%2,%3};"
        : "+f"(d[0]), "+f"(d[1]), "+f"(d[2]), "+f"(d[3])
        : "r"(a[0]), "r"(a[1]), "r"(a[2]), "r"(a[3]), "r"(b[0]), "r"(b[1]));
}

// ---- streaming fp32 -> fp16, both weight tensors in one launch ---------------
__global__ void convert_weights(const float* __restrict__ W1, __half* __restrict__ d1,
                                const float* __restrict__ W2, __half* __restrict__ d2) {
    const size_t NW = (size_t)N_EXP * D_MODEL * D_FF / 8;
    size_t g = (size_t)blockIdx.x * blockDim.x + threadIdx.x;
    const float* s; __half* d;
    if (g < NW) { s = W1; d = d1; }
    else        { s = W2; d = d2; g -= NW; }
    size_t i = g * 8;
    float4 a = *(const float4*)(s + i);
    float4 b = *(const float4*)(s + i + 4);
    __half2 h[4] = { __floats2half2_rn(a.x, a.y), __floats2half2_rn(a.z, a.w),
                     __floats2half2_rn(b.x, b.y), __floats2half2_rn(b.z, b.w) };
    *(uint4*)(d + i) = *(uint4*)h;
}

// ---- router (fused x -> fp16 convert) ----------------------------------------
__global__ void router_kernel(const float* __restrict__ x,
                              const float* __restrict__ Wr) {
    int tok  = (blockIdx.x * blockDim.x + threadIdx.x) >> 5;
    int lane = threadIdx.x & 31;
    if (tok >= T_TOK) return;
    const float* xr = x + (size_t)tok * D_MODEL;
    __half* xh = g_Xh + (size_t)tok * D_MODEL;
    float acc[N_EXP];
#pragma unroll
    for (int e = 0; e < N_EXP; e++) acc[e] = 0.f;
    for (int d = lane; d < D_MODEL; d += 32) {
        float xv = xr[d];
        xh[d] = __float2half_rn(xv);
        float4 w0 = *(const float4*)(Wr + (size_t)d * N_EXP);
        float4 w1 = *(const float4*)(Wr + (size_t)d * N_EXP + 4);
        acc[0] += xv * w0.x; acc[1] += xv * w0.y;
        acc[2] += xv * w0.z; acc[3] += xv * w0.w;
        acc[4] += xv * w1.x; acc[5] += xv * w1.y;
        acc[6] += xv * w1.z; acc[7] += xv * w1.w;
    }
#pragma unroll
    for (int e = 0; e < N_EXP; e++)
#pragma unroll
        for (int o = 16; o > 0; o >>= 1)
            acc[e] += __shfl_xor_sync(0xffffffffu, acc[e], o);
    if (lane == 0) {
        int e1 = 0; float l1 = acc[0];
#pragma unroll
        for (int e = 1; e < N_EXP; e++)
            if (acc[e] > l1) { l1 = acc[e]; e1 = e; }
        int e2 = (e1 == 0) ? 1 : 0; float l2 = acc[e2];
#pragma unroll
        for (int e = 0; e < N_EXP; e++)
            if (e != e1 && acc[e] > l2) { l2 = acc[e]; e2 = e; }
        float g1 = 1.f / (1.f + expf(l2 - l1));
        float g2 = 1.f - g1;
        int p1 = atomicAdd(&g_count[e1], 1);
        g_rows[e1 * T_TOK + p1] = tok; g_gate[e1 * T_TOK + p1] = g1;
        int p2 = atomicAdd(&g_count[e2], 1);
        g_rows[e2 * T_TOK + p2] = tok; g_gate[e2 * T_TOK + p2] = g2;
    }
}

// offsets (recomputed per block) + slot metadata + token->slot map
__global__ void offsets_slots() {
    __shared__ int soff[N_EXP + 1];
    if (threadIdx.x == 0) {
        int s = 0, t = 0;
        for (int e = 0; e < N_EXP; e++) {
            soff[e] = s;
            int ct = (g_count[e] + 127) >> 7;
            if (blockIdx.x == 0)
                for (int m = 0; m < ct; m++) { g_tileE[t] = e; g_tileM[t] = m << 7; t++; }
            s += ct << 7;
        }
        soff[N_EXP] = s;
        if (blockIdx.x == 0) {
            g_ntiles = t;
            for (int e = 0; e <= N_EXP; e++) g_off[e] = soff[e];
        }
    }
    __syncthreads();
    int r = blockIdx.x * 256 + threadIdx.x;
    if (r >= XG_ROWS) return;
    int e = 0;
#pragma unroll
    for (int k = 1; k < N_EXP; k++) if (r >= soff[k]) e = k;
    int i = r - soff[e];
    int tok = (r < soff[N_EXP] && i < g_count[e]) ? g_rows[e * T_TOK + i] : -1;
    g_stok[r]  = tok;
    g_sgate[r] = (tok >= 0) ? g_gate[e * T_TOK + i] : 0.f;
    if (tok >= 0) {
        int p = atomicAdd(&g_tokn[tok], 1);
        g_tokslot[tok * 2 + p] = r;
    }
}

// combine: out[t] = Y0[s1] + Y1[s1] + Y0[s2] + Y1[s2]
__global__ void combine_kernel(float* __restrict__ out) {
    int t = blockIdx.x;
    int s1 = g_tokslot[2 * t], s2 = g_tokslot[2 * t + 1];
    const float* y00 = g_Y + (size_t)s1 * D_MODEL;
    const float* y01 = g_Y + ((size_t)XG_ROWS + s1) * D_MODEL;
    const float* y10 = g_Y + (size_t)s2 * D_MODEL;
    const float* y11 = g_Y + ((size_t)XG_ROWS + s2) * D_MODEL;
    int c = threadIdx.x * 4;
    float4 a = *(const float4*)(y00 + c);
    float4 b = *(const float4*)(y01 + c);
    float4 d = *(const float4*)(y10 + c);
    float4 e = *(const float4*)(y11 + c);
    float4 r;
    r.x = a.x + b.x + d.x + e.x;
    r.y = a.y + b.y + d.y + e.y;
    r.z = a.z + b.z + d.z + e.z;
    r.w = a.w + b.w + d.w + e.w;
    *(float4*)(out + (size_t)t * D_MODEL + c) = r;
}

// ---------------------------------------------------------------------------
// fp16 mma.sync GEMM: 128x128 CTA tile, 128 threads (4 warps, 64x64 warp tile),
// BK=64, 3-stage, 2 CTAs/SM. PASS 1: split-K=2, plain stores into g_Y[chunk].
// Stage (32 KB): A 16K | B 16K
static constexpr int STG_BYTES = 32768;
static constexpr int SMEM_GEMM = 3 * STG_BYTES;

#define LOAD_STAGE(s, ktile) do {                                              \
    uint32_t st_ = sb + (uint32_t)(s) * STG_BYTES;                             \
    size_t koffA_ = (size_t)(ktile) * 128;                                     \
    size_t koffB_ = (size_t)(ktile) * 64 * NTOT * 2;                           \
    _Pragma("unroll")                                                          \
    for (int j_ = 0; j_ < 8; j_++)                                             \
        cp16z(st_ + aphys[j_], asrc[j_] + koffA_, asz[j_]);                    \
    _Pragma("unroll")                                                          \
    for (int j_ = 0; j_ < 8; j_++)                                             \
        cp16(st_ + 16384 + bphys[j_],                                          \
             bsrc + koffB_ + (size_t)j_ * 8 * NTOT * 2);                       \
    asm volatile("cp.async.commit_group;" ::: "memory");                       \
} while (0)

template<int PASS>
__global__ void __launch_bounds__(128, 2)
gemm_mma(const __half* __restrict__ Ax, const __half* __restrict__ Bx,
         const float* __restrict__ bias, float* __restrict__ outY)
{
    constexpr int KTOT = (PASS == 0) ? D_MODEL : D_FF;
    constexpr int NTOT = (PASS == 0) ? D_FF : D_MODEL;
    constexpr int KIT  = (PASS == 0) ? (D_MODEL / 64) : (KCH1 / 64);

    int t = blockIdx.y;
    if (t >= g_ntiles) return;
    int e     = g_tileE[t];
    int rowA0 = g_off[e] + g_tileM[t];
    int n0    = blockIdx.x * 128;
    int kbase = (PASS == 1) ? (int)blockIdx.z * KCH1 : 0;

    extern __shared__ char smem[];
    uint32_t sb = smem_u32(smem);

    int tid = threadIdx.x;
    int wid = tid >> 5, lane = tid & 31;
    int wm = wid >> 1, wn = wid & 1;       // warps 2x2; warp tile 64x64

    // ---- producer constants ----
    // A: 128 rows x 8 chunks; thread owns chunk (tid&7), rows (tid>>3)+16j
    uint32_t acb = (tid & 7) << 4;
    int arb = tid >> 3;                    // 0..15
    uint32_t aphys[8];
    const char* asrc[8];
    uint32_t asz[8];
#pragma unroll
    for (int j = 0; j < 8; j++) {
        int r = arb + 16 * j;
        aphys[j] = SWZ(r * 128 + acb);
        if (PASS == 0) {
            int tk = g_stok[rowA0 + r];
            asz[j]  = (tk >= 0) ? 16u : 0u;
            asrc[j] = (const char*)Ax + ((size_t)max(tk, 0) * KTOT + kbase) * 2 + acb;
        } else {
            asz[j]  = 16u;
            asrc[j] = (const char*)Ax + ((size_t)(rowA0 + r) * KTOT + kbase) * 2 + acb;
        }
    }
    // B: 64 k-rows x 16 chunks (256B rows); thread owns chunk (tid&15), rows (tid>>4)+8j
    int brr = tid >> 4, bc = tid & 15;     // brr 0..7
    uint32_t bphys[8];
#pragma unroll
    for (int j = 0; j < 8; j++) {
        int r = brr + 8 * j;
        bphys[j] = (uint32_t)r * 256 + (uint32_t)((bc ^ (r & 7)) << 4);
    }
    const char* bsrc = (const char*)Bx
        + ((size_t)(e * KTOT + kbase + brr) * NTOT + n0) * 2 + (size_t)bc * 16;

    // ---- consumer fragment constants (B trans) ----
    int krb = (lane & 7) + ((lane >> 4) << 3);
    int nc  = (lane >> 3) & 1;
    uint32_t bck[4];
#pragma unroll
    for (int nt = 0; nt < 4; nt++)
        bck[nt] = (uint32_t)(((wn * 8 + nt * 2 + nc) ^ (lane & 7)) << 4);

    float acc[4][8][4];
#pragma unroll
    for (int a = 0; a < 4; a++)
#pragma unroll
        for (int b = 0; b < 8; b++)
#pragma unroll
            for (int c = 0; c < 4; c++) acc[a][b][c] = 0.f;

    LOAD_STAGE(0, 0);
    LOAD_STAGE(1, 1);

#pragma unroll 1
    for (int kt = 0; kt < KIT; kt++) {
        if (kt + 1 < KIT) asm volatile("cp.async.wait_group 1;" ::: "memory");
        else              asm volatile("cp.async.wait_group 0;" ::: "memory");
        __syncthreads();
        int s = kt % 3;
        if (kt + 2 < KIT) { int s2 = (kt + 2) % 3; LOAD_STAGE(s2, kt + 2); }
        uint32_t sA = sb + (uint32_t)s * STG_BYTES;
        uint32_t sB = sA + 16384;
#pragma unroll
        for (int k16 = 0; k16 < 4; k16++) {
            uint32_t b_f[4][4];
            uint32_t krow = (uint32_t)(k16 * 16 + krb) * 256;
#pragma unroll
            for (int nt = 0; nt < 4; nt++)
                ldsm4t(b_f[nt], sB + krow + bck[nt]);
#pragma unroll
            for (int mt = 0; mt < 4; mt++) {
                uint32_t a_f[4];
                uint32_t ad = sA + SWZ((wm * 64 + mt * 16 + (lane & 15)) * 128
                                       + k16 * 32 + (lane >> 4) * 16);
                ldsm4(a_f, ad);
#pragma unroll
                for (int n8 = 0; n8 < 8; n8++) {
                    int nt = n8 >> 1, hf = n8 & 1;
                    uint32_t bb[2] = { b_f[nt][hf], b_f[nt][2 + hf] };
                    mma_f16(acc[mt][n8], a_f, bb);
                }
            }
        }
    }

    // ---- epilogue ----
    const float* bp = bias + (size_t)e * NTOT;
    float bscale = (PASS == 1 && kbase != 0) ? 0.f : 1.f;   // bias once per output
    float* Yz = (PASS == 1)
        ? outY + (size_t)blockIdx.z * XG_ROWS * D_MODEL : outY;
#pragma unroll
    for (int mt = 0; mt < 4; mt++) {
        int r0 = wm * 64 + mt * 16 + (lane >> 2);
#pragma unroll
        for (int n8 = 0; n8 < 8; n8++) {
            int cg = n0 + wn * 64 + n8 * 8 + (lane & 3) * 2;
            float* a = acc[mt][n8];
            float bb0 = bp[cg] * bscale, bb1 = bp[cg + 1] * bscale;
            int row = rowA0 + r0;
            if (PASS == 0) {
                float v0 = fmaxf(a[0] + bb0, 0.f), v1 = fmaxf(a[1] + bb1, 0.f);
                float v2 = fmaxf(a[2] + bb0, 0.f), v3 = fmaxf(a[3] + bb1, 0.f);
                *(__half2*)(g_H + (size_t)row * D_FF + cg)       = __floats2half2_rn(v0, v1);
                *(__half2*)(g_H + (size_t)(row + 8) * D_FF + cg) = __floats2half2_rn(v2, v3);
            } else {
                float g0 = g_sgate[row], g1 = g_sgate[row + 8];
                float2 w0 = make_float2(g0 * (a[0] + bb0), g0 * (a[1] + bb1));
                float2 w1 = make_float2(g1 * (a[2] + bb0), g1 * (a[3] + bb1));
                *(float2*)(Yz + (size_t)row * D_MODEL + cg)       = w0;
                *(float2*)(Yz + (size_t)(row + 8) * D_MODEL + cg) = w1;
            }
        }
    }
}

// ---------------------------------------------------------------------------
extern "C" void kernel_launch(void* const* d_in, const int* in_sizes, int n_in,
                              void* d_out, int out_size) {
    const float* x  = (const float*)d_in[0];
    const float* Wr = (const float*)d_in[1];
    const float* W1 = (const float*)d_in[2];
    const float* b1 = (const float*)d_in[3];
    const float* W2 = (const float*)d_in[4];
    const float* b2 = (const float*)d_in[5];
    float* out = (float*)d_out;

    void *pW1, *pW2, *pXh, *pH, *pY, *pCnt, *pTokn;
    cudaGetSymbolAddress(&pW1, g_W1h);
    cudaGetSymbolAddress(&pW2, g_W2h);
    cudaGetSymbolAddress(&pXh, g_Xh);
    cudaGetSymbolAddress(&pH,  g_H);
    cudaGetSymbolAddress(&pY,  g_Y);
    cudaGetSymbolAddress(&pCnt,  g_count);
    cudaGetSymbolAddress(&pTokn, g_tokn);

    cudaFuncSetAttribute(gemm_mma<0>, cudaFuncAttributeMaxDynamicSharedMemorySize, SMEM_GEMM);
    cudaFuncSetAttribute(gemm_mma<1>, cudaFuncAttributeMaxDynamicSharedMemorySize, SMEM_GEMM);

    cudaMemsetAsync(pCnt,  0, N_EXP * sizeof(int));
    cudaMemsetAsync(pTokn, 0, T_TOK * sizeof(int));

    convert_weights<<<(int)(2 * ((size_t)N_EXP * D_MODEL * D_FF / 8) / 256), 256>>>(
        W1, (__half*)pW1, W2, (__half*)pW2);

    router_kernel<<<T_TOK / 8, 256>>>(x, Wr);
    offsets_slots<<<XG_ROWS / 256, 256>>>();

    gemm_mma<0><<<dim3(D_FF / 128, MAX_TILES), 128, SMEM_GEMM>>>(
        (const __half*)pXh, (const __half*)pW1, b1, (float*)pH /*unused*/);
    gemm_mma<1><<<dim3(D_MODEL / 128, MAX_TILES, 2), 128, SMEM_GEMM>>>(
        (const __half*)pH, (const __half*)pW2, b2, (float*)pY);

    combine_kernel<<<T_TOK, 256>>>(out);
}

// round 15
// speedup vs baseline: 1.0782x; 1.0289x over previous
#include <cuda_runtime.h>
#include <cuda_fp16.h>
#include <math.h>
#include <stdint.h>

#define D_MODEL 1024
#define D_FF    4096
#define N_EXP   8
#define T_TOK   4096
#define XG_ROWS 9216
#define MAX_TILES 72

// ---- scratch (__device__ globals; no cudaMalloc allowed) --------------------
__device__ int   g_count[N_EXP];
__device__ int   g_off[N_EXP + 1];
__device__ int   g_rows[N_EXP * T_TOK];
__device__ float g_gate[N_EXP * T_TOK];
__device__ int   g_tileE[MAX_TILES];
__device__ int   g_tileM[MAX_TILES];
__device__ int   g_ntiles;
__device__ int   g_stok[XG_ROWS];
__device__ float g_sgate[XG_ROWS];
__device__ int   g_tokn[T_TOK];
__device__ int   g_tokslot[T_TOK * 2];

__device__ __half g_Xh[(size_t)T_TOK * D_MODEL];
__device__ __half g_W1h[(size_t)N_EXP * D_MODEL * D_FF];       // [E][K][N] fp16
__device__ __half g_W2h[(size_t)N_EXP * D_FF * D_MODEL];       // [E][K][N] fp16
__device__ __half g_H[(size_t)XG_ROWS * D_FF];
__device__ float  g_Y[(size_t)XG_ROWS * D_MODEL];              // pass-1 per-slot rows

// ---- helpers ----------------------------------------------------------------
#define SWZ(o) ((o) ^ (((o) >> 3) & 0x70))

__device__ __forceinline__ uint32_t smem_u32(const void* p) {
    uint32_t a;
    asm("{ .reg .u64 t; cvta.to.shared.u64 t, %1; cvt.u32.u64 %0, t; }"
        : "=r"(a) : "l"(p));
    return a;
}
__device__ __forceinline__ void cp16(uint32_t dst, const void* src) {
    asm volatile("cp.async.cg.shared.global [%0], [%1], 16;"
                 :: "r"(dst), "l"(src) : "memory");
}
__device__ __forceinline__ void cp16z(uint32_t dst, const void* src, uint32_t n) {
    asm volatile("cp.async.cg.shared.global [%0], [%1], 16, %2;"
                 :: "r"(dst), "l"(src), "r"(n) : "memory");
}
__device__ __forceinline__ void ldsm4(uint32_t* r, uint32_t addr) {
    asm volatile("ldmatrix.sync.aligned.m8n8.x4.shared.b16 {%0,%1,%2,%3}, [%4];"
                 : "=r"(r[0]), "=r"(r[1]), "=r"(r[2]), "=r"(r[3]) : "r"(addr));
}
__device__ __forceinline__ void ldsm4t(uint32_t* r, uint32_t addr) {
    asm volatile("ldmatrix.sync.aligned.m8n8.x4.trans.shared.b16 {%0,%1,%2,%3}, [%4];"
                 : "=r"(r[0]), "=r"(r[1]), "=r"(r[2]), "=r"(r[3]) : "r"(addr));
}
__device__ __forceinline__ void mma_f16(float* d, const uint32_t* a, const uint32_t* b) {
    asm volatile("mma.sync.aligned.m16n8k16.row.col.f32.f16.f16.f32 "
        "{%0,%1,%2,%3}, {%4,%5,%6,%7}, {%8,%9}, {%0,%1,%2,%3};"
        : "+f"(d[0]), "+f"(d[1]), "+f"(d[2]), "+f"(d[3])
        : "r"(a[0]), "r"(a[1]), "r"(a[2]), "r"(a[3]), "r"(b[0]), "r"(b[1]));
}
__device__ __forceinline__ void cvt8(const float* s, __half* d, size_t i) {
    float4 a = *(const float4*)(s + i);
    float4 b = *(const float4*)(s + i + 4);
    __half2 h[4] = { __floats2half2_rn(a.x, a.y), __floats2half2_rn(a.z, a.w),
                     __floats2half2_rn(b.x, b.y), __floats2half2_rn(b.z, b.w) };
    *(uint4*)(d + i) = *(uint4*)h;
}

// ---- router: logits + top-2 + x->fp16 + W1->fp16 (fused) ----------------------
__global__ void router_kernel(const float* __restrict__ x,
                              const float* __restrict__ Wr,
                              const float* __restrict__ W1,
                              __half* __restrict__ W1h) {
    int tok  = (blockIdx.x * blockDim.x + threadIdx.x) >> 5;
    int lane = threadIdx.x & 31;
    const float* xr = x + (size_t)tok * D_MODEL;
    __half* xh = g_Xh + (size_t)tok * D_MODEL;
    float acc[N_EXP];
#pragma unroll
    for (int e = 0; e < N_EXP; e++) acc[e] = 0.f;
    for (int d = lane; d < D_MODEL; d += 32) {
        float xv = xr[d];
        xh[d] = __float2half_rn(xv);
        float4 w0 = *(const float4*)(Wr + (size_t)d * N_EXP);
        float4 w1 = *(const float4*)(Wr + (size_t)d * N_EXP + 4);
        acc[0] += xv * w0.x; acc[1] += xv * w0.y;
        acc[2] += xv * w0.z; acc[3] += xv * w0.w;
        acc[4] += xv * w1.x; acc[5] += xv * w1.y;
        acc[6] += xv * w1.z; acc[7] += xv * w1.w;
    }
#pragma unroll
    for (int e = 0; e < N_EXP; e++)
#pragma unroll
        for (int o = 16; o > 0; o >>= 1)
            acc[e] += __shfl_xor_sync(0xffffffffu, acc[e], o);
    if (lane == 0) {
        int e1 = 0; float l1 = acc[0];
#pragma unroll
        for (int e = 1; e < N_EXP; e++)
            if (acc[e] > l1) { l1 = acc[e]; e1 = e; }
        int e2 = (e1 == 0) ? 1 : 0; float l2 = acc[e2];
#pragma unroll
        for (int e = 0; e < N_EXP; e++)
            if (e != e1 && acc[e] > l2) { l2 = acc[e]; e2 = e; }
        float g1 = 1.f / (1.f + expf(l2 - l1));
        float g2 = 1.f - g1;
        int p1 = atomicAdd(&g_count[e1], 1);
        g_rows[e1 * T_TOK + p1] = tok; g_gate[e1 * T_TOK + p1] = g1;
        int p2 = atomicAdd(&g_count[e2], 1);
        g_rows[e2 * T_TOK + p2] = tok; g_gate[e2 * T_TOK + p2] = g2;
    }
    // fused W1 fp32 -> fp16 convert (strided over whole grid)
    const size_t NW1 = (size_t)N_EXP * D_MODEL * D_FF;
    size_t gi = ((size_t)blockIdx.x * blockDim.x + threadIdx.x) * 8;
    const size_t gs = (size_t)gridDim.x * blockDim.x * 8;
#pragma unroll 4
    for (; gi < NW1; gi += gs) cvt8(W1, W1h, gi);
}

// offsets (recomputed per block) + slot metadata + token->slot map
__global__ void offsets_slots() {
    __shared__ int soff[N_EXP + 1];
    if (threadIdx.x == 0) {
        int s = 0, t = 0;
        for (int e = 0; e < N_EXP; e++) {
            soff[e] = s;
            int ct = (g_count[e] + 127) >> 7;
            if (blockIdx.x == 0)
                for (int m = 0; m < ct; m++) { g_tileE[t] = e; g_tileM[t] = m << 7; t++; }
            s += ct << 7;
        }
        soff[N_EXP] = s;
        if (blockIdx.x == 0) {
            g_ntiles = t;
            for (int e = 0; e <= N_EXP; e++) g_off[e] = soff[e];
        }
    }
    __syncthreads();
    int r = blockIdx.x * 256 + threadIdx.x;
    if (r >= XG_ROWS) return;
    int e = 0;
#pragma unroll
    for (int k = 1; k < N_EXP; k++) if (r >= soff[k]) e = k;
    int i = r - soff[e];
    int tok = (r < soff[N_EXP] && i < g_count[e]) ? g_rows[e * T_TOK + i] : -1;
    g_stok[r]  = tok;
    g_sgate[r] = (tok >= 0) ? g_gate[e * T_TOK + i] : 0.f;
    if (tok >= 0) {
        int p = atomicAdd(&g_tokn[tok], 1);
        g_tokslot[tok * 2 + p] = r;
    }
}

// combine: out[t] = Y[s1] + Y[s2]   (bias + gate already applied in pass 1)
__global__ void combine_kernel(float* __restrict__ out) {
    int t = blockIdx.x;
    int s1 = g_tokslot[2 * t], s2 = g_tokslot[2 * t + 1];
    int c = threadIdx.x * 4;
    float4 a = *(const float4*)(g_Y + (size_t)s1 * D_MODEL + c);
    float4 b = *(const float4*)(g_Y + (size_t)s2 * D_MODEL + c);
    float4 r;
    r.x = a.x + b.x; r.y = a.y + b.y; r.z = a.z + b.z; r.w = a.w + b.w;
    *(float4*)(out + (size_t)t * D_MODEL + c) = r;
}

// ---------------------------------------------------------------------------
// fp16 mma.sync GEMM, 128 threads, 4 warps (2x2), BK=64, 3-stage, 1 bar/kt.
// PASS 0: CTA 128x128 (warp tile 64x64), K=1024, epilogue -> H fp16.
//         Prologue converts a grid-strided slice of W2 fp32->fp16 (hidden).
// PASS 1: CTA 128x64  (warp tile 64x32), K=4096, epilogue -> Y[slot] stores.
template<int PASS>
__global__ void __launch_bounds__(128, 2)
gemm_mma(const __half* __restrict__ Ax, const __half* __restrict__ Bx,
         const float* __restrict__ bias, float* __restrict__ outY,
         const float* __restrict__ W2src, __half* __restrict__ W2dst)
{
    constexpr int KTOT  = (PASS == 0) ? D_MODEL : D_FF;
    constexpr int NTOT  = (PASS == 0) ? D_FF : D_MODEL;
    constexpr int NTILE = (PASS == 0) ? 128 : 64;
    constexpr int KIT   = KTOT / 64;
    constexpr int BROW  = NTILE * 2;           // B smem row bytes (256 / 128)
    constexpr int BCH   = NTILE / 8;           // 16B chunks per B row (16 / 8)
    constexpr int BITER = (64 * BCH) / 128;    // B cp16 per thread (8 / 4)
    constexpr int BSTR  = 128 / BCH;           // row stride between them (8 / 16)
    constexpr int NTW   = NTILE / 32;          // ldsm4t per k16 per warp (4 / 2)
    constexpr int N8    = 2 * NTW;             // n8 subtiles per warp (8 / 4)
    constexpr int STG   = 16384 + 64 * BROW;   // stage bytes (32K / 24K)

    int tid = threadIdx.x;

    // ---- PASS 0 prologue: convert a slice of W2 (hidden under compute) ----
    if (PASS == 0) {
        const size_t NW2 = (size_t)N_EXP * D_FF * D_MODEL;
        size_t gi = ((size_t)(blockIdx.y * gridDim.x + blockIdx.x) * 128 + tid) * 8;
        const size_t gs = (size_t)gridDim.x * gridDim.y * 128 * 8;
        for (; gi < NW2; gi += gs) cvt8(W2src, W2dst, gi);
    }

    int t = blockIdx.y;
    if (t >= g_ntiles) return;
    int e     = g_tileE[t];
    int rowA0 = g_off[e] + g_tileM[t];
    int n0    = blockIdx.x * NTILE;

    extern __shared__ char smem[];
    uint32_t sb = smem_u32(smem);

    int wid = tid >> 5, lane = tid & 31;
    int wm = wid >> 1, wn = wid & 1;           // warps 2x2

    // ---- producer constants ----
    uint32_t acb = (tid & 7) << 4;
    int arb = tid >> 3;                        // 0..15
    uint32_t aphys[8];
    const char* asrc[8];
    uint32_t asz[8];
#pragma unroll
    for (int j = 0; j < 8; j++) {
        int r = arb + 16 * j;
        aphys[j] = SWZ(r * 128 + acb);
        if (PASS == 0) {
            int tk = g_stok[rowA0 + r];
            asz[j]  = (tk >= 0) ? 16u : 0u;
            asrc[j] = (const char*)Ax + ((size_t)max(tk, 0) * KTOT) * 2 + acb;
        } else {
            asz[j]  = 16u;
            asrc[j] = (const char*)Ax + ((size_t)(rowA0 + r) * KTOT) * 2 + acb;
        }
    }
    int brr = tid / BCH, bc = tid % BCH;
    uint32_t bphys[BITER];
#pragma unroll
    for (int j = 0; j < BITER; j++) {
        int r = brr + BSTR * j;
        bphys[j] = (uint32_t)r * BROW + (uint32_t)((bc ^ (r & 7)) << 4);
    }
    const char* bsrc = (const char*)Bx
        + ((size_t)(e * KTOT + brr) * NTOT + n0) * 2 + (size_t)bc * 16;

    // ---- consumer fragment constants (B trans) ----
    int krb = (lane & 7) + ((lane >> 4) << 3);
    int nc  = (lane >> 3) & 1;
    uint32_t bck[NTW];
#pragma unroll
    for (int nt = 0; nt < NTW; nt++)
        bck[nt] = (uint32_t)(((wn * 2 * NTW + nt * 2 + nc) ^ (lane & 7)) << 4);

    float acc[4][N8][4];
#pragma unroll
    for (int a = 0; a < 4; a++)
#pragma unroll
        for (int b = 0; b < N8; b++)
#pragma unroll
            for (int c = 0; c < 4; c++) acc[a][b][c] = 0.f;

#define LOAD_STAGE(s, ktile) do {                                              \
    uint32_t st_ = sb + (uint32_t)(s) * STG;                                   \
    size_t koffA_ = (size_t)(ktile) * 128;                                     \
    size_t koffB_ = (size_t)(ktile) * 64 * NTOT * 2;                           \
    _Pragma("unroll")                                                          \
    for (int j_ = 0; j_ < 8; j_++)                                             \
        cp16z(st_ + aphys[j_], asrc[j_] + koffA_, asz[j_]);                    \
    _Pragma("unroll")                                                          \
    for (int j_ = 0; j_ < BITER; j_++)                                         \
        cp16(st_ + 16384 + bphys[j_],                                          \
             bsrc + koffB_ + (size_t)j_ * BSTR * NTOT * 2);                    \
    asm volatile("cp.async.commit_group;" ::: "memory");                       \
} while (0)

    LOAD_STAGE(0, 0);
    LOAD_STAGE(1, 1);

#pragma unroll 1
    for (int kt = 0; kt < KIT; kt++) {
        if (kt + 1 < KIT) asm volatile("cp.async.wait_group 1;" ::: "memory");
        else              asm volatile("cp.async.wait_group 0;" ::: "memory");
        __syncthreads();
        int s = kt % 3;
        if (kt + 2 < KIT) { int s2 = (kt + 2) % 3; LOAD_STAGE(s2, kt + 2); }
        uint32_t sA = sb + (uint32_t)s * STG;
        uint32_t sB = sA + 16384;
#pragma unroll
        for (int k16 = 0; k16 < 4; k16++) {
            uint32_t b_f[NTW][4];
            uint32_t krow = (uint32_t)(k16 * 16 + krb) * BROW;
#pragma unroll
            for (int nt = 0; nt < NTW; nt++)
                ldsm4t(b_f[nt], sB + krow + bck[nt]);
#pragma unroll
            for (int mt = 0; mt < 4; mt++) {
                uint32_t a_f[4];
                uint32_t ad = sA + SWZ((wm * 64 + mt * 16 + (lane & 15)) * 128
                                       + k16 * 32 + (lane >> 4) * 16);
                ldsm4(a_f, ad);
#pragma unroll
                for (int n8 = 0; n8 < N8; n8++) {
                    int nt = n8 >> 1, hf = n8 & 1;
                    uint32_t bb[2] = { b_f[nt][hf], b_f[nt][2 + hf] };
                    mma_f16(acc[mt][n8], a_f, bb);
                }
            }
        }
    }
#undef LOAD_STAGE

    // ---- epilogue ----
    const float* bp = bias + (size_t)e * NTOT;
#pragma unroll
    for (int mt = 0; mt < 4; mt++) {
        int r0 = wm * 64 + mt * 16 + (lane >> 2);
#pragma unroll
        for (int n8 = 0; n8 < N8; n8++) {
            int cg = n0 + wn * (NTILE / 2) + n8 * 8 + (lane & 3) * 2;
            float* a = acc[mt][n8];
            float bb0 = bp[cg], bb1 = bp[cg + 1];
            int row = rowA0 + r0;
            if (PASS == 0) {
                float v0 = fmaxf(a[0] + bb0, 0.f), v1 = fmaxf(a[1] + bb1, 0.f);
                float v2 = fmaxf(a[2] + bb0, 0.f), v3 = fmaxf(a[3] + bb1, 0.f);
                *(__half2*)(g_H + (size_t)row * D_FF + cg)       = __floats2half2_rn(v0, v1);
                *(__half2*)(g_H + (size_t)(row + 8) * D_FF + cg) = __floats2half2_rn(v2, v3);
            } else {
                float g0 = g_sgate[row], g1 = g_sgate[row + 8];
                float2 w0 = make_float2(g0 * (a[0] + bb0), g0 * (a[1] + bb1));
                float2 w1 = make_float2(g1 * (a[2] + bb0), g1 * (a[3] + bb1));
                *(float2*)(outY + (size_t)row * D_MODEL + cg)       = w0;
                *(float2*)(outY + (size_t)(row + 8) * D_MODEL + cg) = w1;
            }
        }
    }
}

// ---------------------------------------------------------------------------
extern "C" void kernel_launch(void* const* d_in, const int* in_sizes, int n_in,
                              void* d_out, int out_size) {
    const float* x  = (const float*)d_in[0];
    const float* Wr = (const float*)d_in[1];
    const float* W1 = (const float*)d_in[2];
    const float* b1 = (const float*)d_in[3];
    const float* W2 = (const float*)d_in[4];
    const float* b2 = (const float*)d_in[5];
    float* out = (float*)d_out;

    void *pW1, *pW2, *pXh, *pH, *pY, *pCnt, *pTokn;
    cudaGetSymbolAddress(&pW1, g_W1h);
    cudaGetSymbolAddress(&pW2, g_W2h);
    cudaGetSymbolAddress(&pXh, g_Xh);
    cudaGetSymbolAddress(&pH,  g_H);
    cudaGetSymbolAddress(&pY,  g_Y);
    cudaGetSymbolAddress(&pCnt,  g_count);
    cudaGetSymbolAddress(&pTokn, g_tokn);

    static constexpr int SMEM0 = 3 * (16384 + 64 * 256);   // 98304
    static constexpr int SMEM1 = 3 * (16384 + 64 * 128);   // 73728
    cudaFuncSetAttribute(gemm_mma<0>, cudaFuncAttributeMaxDynamicSharedMemorySize, SMEM0);
    cudaFuncSetAttribute(gemm_mma<1>, cudaFuncAttributeMaxDynamicSharedMemorySize, SMEM1);

    cudaMemsetAsync(pCnt,  0, N_EXP * sizeof(int));
    cudaMemsetAsync(pTokn, 0, T_TOK * sizeof(int));

    router_kernel<<<T_TOK / 8, 256>>>(x, Wr, W1, (__half*)pW1);
    offsets_slots<<<XG_ROWS / 256, 256>>>();

    gemm_mma<0><<<dim3(D_FF / 128, MAX_TILES), 128, SMEM0>>>(
        (const __half*)pXh, (const __half*)pW1, b1, (float*)pH /*unused*/,
        W2, (__half*)pW2);
    gemm_mma<1><<<dim3(D_MODEL / 64, MAX_TILES), 128, SMEM1>>>(
        (const __half*)pH, (const __half*)pW2, b2, (float*)pY,
        nullptr, nullptr);

    combine_kernel<<<T_TOK, 256>>>(out);
}